// round 5
// baseline (speedup 1.0000x reference)
#include <cuda_runtime.h>

// SoftMSMLoss: soft-MSM DP, gamma=1, c=1, 512x512, B=64.
// 2 blocks per problem (256 rows each), 128 blocks total. Branch-free
// warp-pipelined wavefront in log2-scaled domain; cross-block handoff of the
// band-boundary row through L2 with chunked flags + register prefetch.

#define TLEN 512
#define NWARP 8    // warps per block (256 threads = half problem)
#define NBATCH 64
#define CHUNK 8    // in-block SMEM handoff granularity
#define GCHUNK 32  // cross-block handoff granularity
#define NSTEP 544  // covers s=0..542; padded to unroll-8 multiple
#define BIG 1e30f
#define LOG2E 1.4426950408889634f
#define LN2 0.6931471805599453f

__device__ float g_costs[NBATCH];
__device__ float g_hand[NBATCH][TLEN];
__device__ volatile int g_flag[NBATCH];  // monotonic per launch; consumer resets
__device__ int g_done;

__global__ __launch_bounds__(256, 1) void soft_msm_kernel(
    const float* __restrict__ x, const float* __restrict__ y,
    float* __restrict__ out) {
    __shared__ float4 scol[TLEN];            // {y_j, dyb_j, Eb2_j, pad}
    __shared__ float hand[NWARP - 1][TLEN];  // in-block boundary rows
    __shared__ volatile int flags[NWARP - 1];

    const int t = threadIdx.x;  // 0..255
    const int w = t >> 5;
    const int l = t & 31;
    const int bb = blockIdx.x;
    const int b = bb >> 1;
    const int half = bb & 1;
    const int row = half * 256 + t;
    const float* xb = x + b * TLEN;
    const float* yb = y + b * TLEN;

    if (t < NWARP - 1) flags[t] = 0;
    for (int jj = t; jj < TLEN; jj += 256) {
        const float yv = yb[jj];
        const float ym1 = (jj > 0) ? yb[jj - 1] : yv;
        const float dyb = yv - ym1;
        const float eb = (jj > 0) ? exp2f(-LOG2E * dyb * dyb) : 0.0f;
        scol[jj] = make_float4(yv, dyb, eb, 0.0f);
    }
    const float xi = xb[row];
    float myDxa = 0.0f, myEa = 0.0f;
    if (row > 0) {
        myDxa = xi - xb[row - 1];
        myEa = exp2f(-LOG2E * myDxa * myDxa);
    }
    __syncthreads();

    float cij = BIG;                           // C'(i, j-1)
    float upPrev = (row == 0) ? 0.0f : BIG;    // becomes diag C'(i-1,j-1)
    const bool isT0 = (row == 0);
    const bool consW = (half == 1) && (w == 0);       // cross-block consumer warp
    const bool sProducer = (l == 31) && (w < NWARP - 1);
    const bool gProducer = (half == 0) && (t == 255);  // global row 255
    volatile int* vflag = &g_flag[b];
    const float* ghb = &g_hand[b][0];
    float* ghw = &g_hand[b][0];

    float gcur = 0.0f, gnext = 0.0f;
    int availG = 0, availS = 0;
    if (consW) {  // prefetch first cross-block chunk
        int v;
        while ((v = *vflag) < GCHUNK) __nanosleep(100);
        availG = v;
        __threadfence();
        gnext = __ldcg(ghb + l);
    }

#pragma unroll 8
    for (int s = 0; s < NSTEP; ++s) {
        if (consW && (s & (GCHUNK - 1)) == 0) {  // rotate + prefetch next chunk
            gcur = gnext;
            const int nb = s + GCHUNK;
            if (nb < TLEN) {
                const int need = nb + GCHUNK;  // <= 512
                if (availG < need) {
                    int v;
                    while ((v = *vflag) < need) __nanosleep(100);
                    availG = v;
                    __threadfence();
                }
                gnext = __ldcg(ghb + nb + l);
            }
        }
        if (w > 0 && s < TLEN && (s & (CHUNK - 1)) == 0) {
            int need = s + CHUNK;
            if (need > TLEN) need = TLEN;
            if (availS < need) {
                int v;
                while ((v = flags[w - 1]) < need) __nanosleep(40);
                availS = v;
                __threadfence_block();
            }
        }

        float up = __shfl_up_sync(0xffffffffu, cij, 1);  // C'(i-1, j)
        const int j = s - l;
        const bool active = ((unsigned)j < (unsigned)TLEN);
        const int jc = active ? j : 0;
        if (isT0) up = BIG;
        if (w > 0 && l == 0 && half == 0) up = hand[w - 1][jc];
        if (w > 0 && l == 0 && half == 1) up = hand[w - 1][jc];
        if (consW) {
            const float hv = __shfl_sync(0xffffffffu, gcur, s & (GCHUNK - 1));
            if (l == 0) up = hv;
        }
        const float diag = upPrev;
        upPrev = up;

        const float4 cv = scol[jc];
        const float bm = xi - cv.x;
        const float matchp = (LOG2E * bm) * bm;  // match * log2(e)
        const float Em = exp2f(-matchp);

        const float uu = myDxa * bm;
        const float wu = 0.5f + 0.5f * uu * rsqrtf(uu * uu + 1e-9f);
        const float du = up + (LOG2E - wu * __log2f(myEa + Em));

        const float ul = -cv.y * bm;
        const float wl = 0.5f + 0.5f * ul * rsqrtf(ul * ul + 1e-9f);
        const float dl = cij + (LOG2E - wl * __log2f(cv.z + Em));

        const float dd = diag + matchp;
        const float m = fminf(dd, fminf(du, dl));
        const float ssum = exp2f(m - dd) + exp2f(m - du) + exp2f(m - dl);
        const float cnew = m - __log2f(ssum);
        cij = active ? cnew : cij;

        if (sProducer) hand[w][jc] = cij;
        if (sProducer && active && ((j & (CHUNK - 1)) == CHUNK - 1)) {
            __threadfence_block();
            flags[w] = j + 1;
        }
        if (gProducer && active) ghw[j] = cij;
        if (gProducer && active && ((j & (GCHUNK - 1)) == GCHUNK - 1)) {
            __threadfence();
            *vflag = j + 1;
        }
    }

    if (half == 1 && t == 255) {  // global row 511: final cost
        g_costs[b] = cij * LN2;   // unscale
        *vflag = 0;               // reset for next graph replay
        __threadfence();
        const int old = atomicAdd(&g_done, 1);
        if (old == NBATCH - 1) {
            __threadfence();
            float v = 0.0f;
#pragma unroll
            for (int i = 0; i < NBATCH; ++i) v += g_costs[i];
            out[0] = v * (1.0f / (float)NBATCH);
            atomicExch(&g_done, 0);
        }
    }
}

extern "C" void kernel_launch(void* const* d_in, const int* in_sizes, int n_in,
                              void* d_out, int out_size) {
    const float* x = (const float*)d_in[0];
    const float* y = (const float*)d_in[1];
    float* out = (float*)d_out;
    soft_msm_kernel<<<2 * NBATCH, 256>>>(x, y, out);
}

// round 6
// speedup vs baseline: 1.1923x; 1.1923x over previous
#include <cuda_runtime.h>
#include <cooperative_groups.h>

namespace cg = cooperative_groups;

// SoftMSMLoss: soft-MSM DP, gamma=1, c=1, 512x512, B=64.
// 2-CTA cluster per problem (256 rows each), DSMEM push handoff of the
// boundary row; branch-free warp-pipelined wavefront in log2 domain.

#define TLEN 512
#define NWARP 8    // warps per CTA
#define NBATCH 64
#define CHUNK 8    // in-block SMEM handoff granularity
#define GCHUNK 16  // cross-CTA handoff granularity
#define NSTEP 544
#define BIG 1e30f
#define LOG2E 1.4426950408889634f
#define LN2 0.6931471805599453f

__device__ float g_costs[NBATCH];
__device__ int g_done;

__global__ __launch_bounds__(256, 1) __cluster_dims__(2, 1, 1)
void soft_msm_kernel(const float* __restrict__ x, const float* __restrict__ y,
                     float* __restrict__ out) {
    __shared__ float4 scol[TLEN];            // {y_j, dyb_j, Eb_j, pad}
    __shared__ float hand[NWARP - 1][TLEN];  // in-block boundary rows
    __shared__ volatile int flags[NWARP - 1];
    __shared__ float gh[TLEN];       // cross-CTA boundary row (rank1's copy)
    __shared__ int ghflag;           // cross-CTA flag (rank1's copy)

    cg::cluster_group cluster = cg::this_cluster();
    const int rank = (int)cluster.block_rank();

    const int t = threadIdx.x;  // 0..255
    const int w = t >> 5;
    const int l = t & 31;
    const int b = blockIdx.x >> 1;
    const int row = rank * 256 + t;
    const float* xb = x + b * TLEN;
    const float* yb = y + b * TLEN;

    if (t < NWARP - 1) flags[t] = 0;
    if (t == 0) ghflag = 0;
    for (int jj = t; jj < TLEN; jj += 256) {
        const float yv = yb[jj];
        const float ym1 = (jj > 0) ? yb[jj - 1] : yv;
        const float dyb = yv - ym1;
        const float eb = (jj > 0) ? exp2f(-LOG2E * dyb * dyb) : 0.0f;
        scol[jj] = make_float4(yv, dyb, eb, 0.0f);
    }
    const float xi = xb[row];
    float myDxa = 0.0f, myEa = 0.0f;
    if (row > 0) {
        myDxa = xi - xb[row - 1];
        myEa = exp2f(-LOG2E * myDxa * myDxa);
    }
    __syncthreads();
    cluster.sync();  // rank1's gh/ghflag initialized before rank0 pushes

    float* remGH = (float*)cluster.map_shared_rank((void*)gh, 1);
    int* remFlag = (int*)cluster.map_shared_rank((void*)&ghflag, 1);

    float cij = BIG;                            // C'(i, j-1)
    float upPrev = (row == 0) ? 0.0f : BIG;     // becomes diag C'(i-1,j-1)
    const bool isT0 = (row == 0);
    const bool crossCons = (rank == 1) && (w == 0);
    const bool sProducer = (l == 31) && (w < NWARP - 1);
    const bool gProducer = (rank == 0) && (t == 255);
    int availS = 0, availG = 0;

#pragma unroll 8
    for (int s = 0; s < NSTEP; ++s) {
        if (crossCons && s < TLEN && (s & (GCHUNK - 1)) == 0) {
            const int need = s + GCHUNK;  // <= TLEN
            if (availG < need) {
                while ((availG = *(volatile int*)&ghflag) < need)
                    __nanosleep(20);
                asm volatile("fence.acq_rel.cluster;" ::: "memory");
            }
        }
        if (w > 0 && s < TLEN && (s & (CHUNK - 1)) == 0) {
            int need = s + CHUNK;
            if (need > TLEN) need = TLEN;
            if (availS < need) {
                while ((availS = flags[w - 1]) < need) __nanosleep(20);
                __threadfence_block();
            }
        }

        float up = __shfl_up_sync(0xffffffffu, cij, 1);  // C'(i-1, j)
        const int j = s - l;
        const bool active = ((unsigned)j < (unsigned)TLEN);
        const int jc = active ? j : 0;
        if (isT0) up = BIG;
        if (w > 0 && l == 0) up = hand[w - 1][jc];
        if (crossCons && l == 0) up = gh[jc];
        const float diag = upPrev;
        upPrev = up;

        const float4 cv = scol[jc];
        const float bm = xi - cv.x;
        const float matchp = (LOG2E * bm) * bm;
        const float Em = exp2f(-matchp);

        const float uu = myDxa * bm;
        const float wu = 0.5f + 0.5f * uu * rsqrtf(uu * uu + 1e-9f);
        const float du = up + (LOG2E - wu * __log2f(myEa + Em));

        const float ul = -cv.y * bm;
        const float wl = 0.5f + 0.5f * ul * rsqrtf(ul * ul + 1e-9f);
        const float dl = cij + (LOG2E - wl * __log2f(cv.z + Em));

        const float dd = diag + matchp;
        const float m = fminf(dd, fminf(du, dl));
        const float ssum = exp2f(m - dd) + exp2f(m - du) + exp2f(m - dl);
        const float cnew = m - __log2f(ssum);
        cij = active ? cnew : cij;

        if (sProducer) hand[w][jc] = cij;
        if (sProducer && active && ((j & (CHUNK - 1)) == CHUNK - 1)) {
            __threadfence_block();
            flags[w] = j + 1;
        }
        if (gProducer && active) remGH[j] = cij;  // DSMEM push, off-chain
        if (gProducer && active && ((j & (GCHUNK - 1)) == GCHUNK - 1)) {
            asm volatile("fence.acq_rel.cluster;" ::: "memory");
            *(volatile int*)remFlag = j + 1;
        }
    }

    cluster.sync();  // DSMEM lifetime: rank0 idles while rank1 drains

    if (rank == 1 && t == 255) {  // global row 511: final cost
        g_costs[b] = cij * LN2;
        __threadfence();
        const int old = atomicAdd(&g_done, 1);
        if (old == NBATCH - 1) {
            __threadfence();
            float v = 0.0f;
#pragma unroll
            for (int i = 0; i < NBATCH; ++i) v += g_costs[i];
            out[0] = v * (1.0f / (float)NBATCH);
            atomicExch(&g_done, 0);
        }
    }
}

extern "C" void kernel_launch(void* const* d_in, const int* in_sizes, int n_in,
                              void* d_out, int out_size) {
    const float* x = (const float*)d_in[0];
    const float* y = (const float*)d_in[1];
    float* out = (float*)d_out;
    soft_msm_kernel<<<2 * NBATCH, 256>>>(x, y, out);
}

// round 7
// speedup vs baseline: 1.6131x; 1.3529x over previous
#include <cuda_runtime.h>

// SoftMSMLoss: soft-MSM DP, gamma=1, c=1, 512x512, B=64.
// Probability-domain wavefront: P = e^{-C} tracked as (sv in [1,2), int exp).
// softmin3 becomes a 3-term FMA sum; hard sign gate with exact rare-path
// fallback. 1 MUFU per cell. One 512-thread block per problem.

#define TLEN 512
#define NWARP 16
#define NBATCH 64
#define CHUNK 8
#define NSTEP 544
#define LOG2E 1.4426950408889634f
#define LN2 0.6931471805599453f
#define KCONST 0.36787944117144233f  // e^{-c}, c=1
#define SENT (-(1 << 28))
#define GATE_T 1e-3f

__device__ float g_costs[NBATCH];
__device__ int g_done;

__device__ __forceinline__ float scale2(int d) {
    // 2^d for d <= 0 (clamped to 0 below 2^-127)
    int b = 127 + d;
    b = max(b, 0);
    return __int_as_float(b << 23);
}

__global__ __launch_bounds__(512, 1) void soft_msm_kernel(
    const float* __restrict__ x, const float* __restrict__ y,
    float* __restrict__ out) {
    __shared__ float4 scol[TLEN];  // {y_j, dyb_j, Eb_j, K*Eb_j}
    __shared__ float hand_s[NWARP - 1][TLEN];
    __shared__ int hand_m[NWARP - 1][TLEN];
    __shared__ volatile int flags[NWARP - 1];
    __shared__ float sx[TLEN];

    const int t = threadIdx.x;
    const int w = t >> 5;
    const int l = t & 31;
    const int b = blockIdx.x;

    const float xi = x[b * TLEN + t];
    const float yown = y[b * TLEN + t];
    sx[t] = xi;
    scol[t].x = yown;
    if (t < NWARP - 1) flags[t] = 0;
    __syncthreads();

    // per-row constants (up transition)
    float myDxa, myEa, myEaK;
    if (t > 0) {
        myDxa = xi - sx[t - 1];
        myEa = exp2f(-LOG2E * myDxa * myDxa);
        myEaK = myEa * KCONST;
    } else {
        myDxa = 1e9f;  // forces |uu| large; tU is 0 anyway (svU sentinel)
        myEa = 0.0f;
        myEaK = 0.0f;
    }
    const float ym1 = (t > 0) ? scol[t - 1].x : yown;
    __syncthreads();
    {
        if (t > 0) {
            const float dyb = yown - ym1;
            const float eb = exp2f(-LOG2E * dyb * dyb);
            scol[t] = make_float4(yown, dyb, eb, eb * KCONST);
        } else {
            scol[t] = make_float4(yown, 1e9f, 0.0f, 0.0f);  // tL is 0 at j=0
        }
    }
    __syncthreads();

    float svC = 0.0f;  // own P(i, j-1) mantissa
    int miC = SENT;
    float svD = (t == 0) ? 1.0f : 0.0f;  // rolling up -> diag
    int miD_ = (t == 0) ? 0 : SENT;
    const bool isT0 = (t == 0);
    const bool isCons = (l == 0) && (w > 0);
    const bool isProd = (l == 31) && (w < NWARP - 1);
    int availS = 0;

#pragma unroll 8
    for (int s = 0; s < NSTEP; ++s) {
        if (w > 0 && s < TLEN && (s & (CHUNK - 1)) == 0) {
            int need = s + CHUNK;
            if (need > TLEN) need = TLEN;
            if (availS < need) {
                while ((availS = flags[w - 1]) < need) __nanosleep(20);
                __threadfence_block();
            }
        }

        float svU = __shfl_up_sync(0xffffffffu, svC, 1);
        int miU = __shfl_up_sync(0xffffffffu, miC, 1);
        const int j = s - l;
        const bool active = ((unsigned)j < (unsigned)TLEN);
        const int jc = active ? j : 0;
        if (isT0) { svU = 0.0f; miU = SENT; }
        if (isCons) { svU = hand_s[w - 1][jc]; miU = hand_m[w - 1][jc]; }
        const float dgS = svD;  // diag P(i-1, j-1)
        const int dgM = miD_;
        svD = svU;
        miD_ = miU;

        const float4 cv = scol[jc];
        const float bm = xi - cv.x;
        const float matchp = (LOG2E * bm) * bm;
        const float Em = exp2f(-matchp);  // e^{-match}
        const float EmK = Em * KCONST;

        const float uu = myDxa * bm;
        const float ul = -cv.y * bm;
        float selU = (uu > 0.0f) ? (myEaK + EmK) : KCONST;
        float selL = (ul > 0.0f) ? (cv.w + EmK) : KCONST;
        if (fabsf(uu) < GATE_T || fabsf(ul) < GATE_T) {  // exact smooth gate
            const float wu = 0.5f + 0.5f * uu * rsqrtf(uu * uu + 1e-9f);
            selU = KCONST * exp2f(wu * __log2f(myEa + Em));
            const float wl = 0.5f + 0.5f * ul * rsqrtf(ul * ul + 1e-9f);
            selL = KCONST * exp2f(wl * __log2f(cv.z + Em));
        }

        const float tD = dgS * Em;
        const float tU = svU * selU;
        const float tL = svC * selL;
        const int mh = max(dgM, max(miU, miC));
        const float pD = scale2(dgM - mh);
        const float pU = scale2(miU - mh);
        const float pL = scale2(miC - mh);
        const float ssum = fmaf(tD, pD, fmaf(tU, pU, tL * pL));

        const int sb = __float_as_int(ssum);
        const int e = (sb >> 23) - 127;
        const float svN = __int_as_float((sb & 0x007FFFFF) | 0x3F800000);
        const int miN = mh + e;
        if (active) { svC = svN; miC = miN; }

        if (isProd) { hand_s[w][jc] = svC; hand_m[w][jc] = miC; }
        if (isProd && active && ((j & (CHUNK - 1)) == CHUNK - 1)) {
            __threadfence_block();
            flags[w] = j + 1;
        }
    }

    if (t == TLEN - 1) {  // C = -ln(P) = -(mi + log2(sv)) * ln2
        g_costs[b] = -((float)miC + __log2f(svC)) * LN2;
        __threadfence();
        const int old = atomicAdd(&g_done, 1);
        if (old == NBATCH - 1) {
            __threadfence();
            float v = 0.0f;
#pragma unroll
            for (int i = 0; i < NBATCH; ++i) v += g_costs[i];
            out[0] = v * (1.0f / (float)NBATCH);
            atomicExch(&g_done, 0);
        }
    }
}

extern "C" void kernel_launch(void* const* d_in, const int* in_sizes, int n_in,
                              void* d_out, int out_size) {
    const float* x = (const float*)d_in[0];
    const float* y = (const float*)d_in[1];
    float* out = (float*)d_out;
    soft_msm_kernel<<<NBATCH, TLEN>>>(x, y, out);
}

// round 8
// speedup vs baseline: 1.7292x; 1.0720x over previous
#include <cuda_runtime.h>

// SoftMSMLoss: soft-MSM DP, gamma=1, c=1, 512x512, B=64.
// Probability-domain wavefront (P = e^{-C} as (mantissa, int exp)), hard sign
// gate with exact rare-path fallback. 2 rows per thread: 256 threads, 8 warps;
// shuffle/handoff/loop overhead amortized over 2 cells, ILP between cells.

#define TLEN 512
#define NWARP 8
#define NBATCH 64
#define CHUNK 8
#define NSTEP 544
#define LOG2E 1.4426950408889634f
#define LN2 0.6931471805599453f
#define KCONST 0.36787944117144233f  // e^{-c}, c=1
#define SENT (-(1 << 28))
#define GATE_T 1e-3f

__device__ float g_costs[NBATCH];
__device__ int g_done;

__device__ __forceinline__ float scale2(int d) {  // 2^d, d<=0, underflow->0
    int bb = 127 + d;
    bb = max(bb, 0);
    return __int_as_float(bb << 23);
}

struct PV { float sv; int mi; };

// One DP cell in probability domain.
__device__ __forceinline__ PV cell(float svU, int miU, float svD, int miD,
                                   float svL, int miL, float xi, float dxa,
                                   float Ea, float EaK, float4 cv) {
    const float bm = xi - cv.x;
    const float matchp = (LOG2E * bm) * bm;
    const float Em = exp2f(-matchp);
    const float EmK = Em * KCONST;

    const float uu = dxa * bm;
    const float ul = -cv.y * bm;
    float selU = (uu > 0.0f) ? (EaK + EmK) : KCONST;
    float selL = (ul > 0.0f) ? (cv.w + EmK) : KCONST;
    if (fabsf(uu) < GATE_T || fabsf(ul) < GATE_T) {  // exact smooth gate
        const float wu = 0.5f + 0.5f * uu * rsqrtf(uu * uu + 1e-9f);
        selU = KCONST * exp2f(wu * __log2f(Ea + Em));
        const float wl = 0.5f + 0.5f * ul * rsqrtf(ul * ul + 1e-9f);
        selL = KCONST * exp2f(wl * __log2f(cv.z + Em));
    }

    const float tD = svD * Em;
    const float tU = svU * selU;
    const float tL = svL * selL;
    const int mh = max(miD, max(miU, miL));
    const float ssum = fmaf(tD, scale2(miD - mh),
                            fmaf(tU, scale2(miU - mh), tL * scale2(miL - mh)));
    const int sb = __float_as_int(ssum);
    PV r;
    r.sv = __int_as_float((sb & 0x007FFFFF) | 0x3F800000);
    r.mi = mh + ((sb >> 23) - 127);
    return r;
}

__global__ __launch_bounds__(256, 1) void soft_msm_kernel(
    const float* __restrict__ x, const float* __restrict__ y,
    float* __restrict__ out) {
    __shared__ float4 scol[TLEN];  // {y_j, dyb_j, Eb_j, K*Eb_j}
    __shared__ float hand_s[NWARP - 1][TLEN];
    __shared__ int hand_m[NWARP - 1][TLEN];
    __shared__ volatile int flags[NWARP - 1];

    const int t = threadIdx.x;  // 0..255; owns rows 2t, 2t+1
    const int w = t >> 5;
    const int l = t & 31;
    const int b = blockIdx.x;
    const float* xb = x + b * TLEN;
    const float* yb = y + b * TLEN;

    if (t < NWARP - 1) flags[t] = 0;
    for (int jj = t; jj < TLEN; jj += 256) {
        const float yv = yb[jj];
        if (jj > 0) {
            const float dyb = yv - yb[jj - 1];
            const float eb = exp2f(-LOG2E * dyb * dyb);
            scol[jj] = make_float4(yv, dyb, eb, eb * KCONST);
        } else {
            scol[jj] = make_float4(yv, 1e9f, 0.0f, 0.0f);
        }
    }
    // per-row constants for both rows
    const int r0 = 2 * t, r1 = 2 * t + 1;
    const float xi0 = xb[r0], xi1 = xb[r1];
    float dxa0, Ea0, Ea0K;
    if (r0 > 0) {
        dxa0 = xi0 - xb[r0 - 1];
        Ea0 = exp2f(-LOG2E * dxa0 * dxa0);
        Ea0K = Ea0 * KCONST;
    } else {
        dxa0 = 1e9f; Ea0 = 0.0f; Ea0K = 0.0f;
    }
    const float dxa1 = xi1 - xi0;
    const float Ea1 = exp2f(-LOG2E * dxa1 * dxa1);
    const float Ea1K = Ea1 * KCONST;
    __syncthreads();

    float svC0 = 0.0f, svC1 = 0.0f;  // P(r, j-1)
    int miC0 = SENT, miC1 = SENT;
    float svD0 = (t == 0) ? 1.0f : 0.0f;  // rolling up->diag for row0
    int miD0 = (t == 0) ? 0 : SENT;
    const bool isT0 = (t == 0);
    const bool isCons = (l == 0) && (w > 0);
    const bool isProd = (l == 31) && (w < NWARP - 1);
    int availS = 0;

#pragma unroll 8
    for (int s = 0; s < NSTEP; ++s) {
        if (w > 0 && s < TLEN && (s & (CHUNK - 1)) == 0) {
            int need = s + CHUNK;
            if (need > TLEN) need = TLEN;
            if (availS < need) {
                while ((availS = flags[w - 1]) < need) __nanosleep(20);
                __threadfence_block();
            }
        }

        float svU0 = __shfl_up_sync(0xffffffffu, svC1, 1);  // row above r0
        int miU0 = __shfl_up_sync(0xffffffffu, miC1, 1);
        const int j = s - l;
        const bool active = ((unsigned)j < (unsigned)TLEN);
        const int jc = active ? j : 0;
        if (isT0) { svU0 = 0.0f; miU0 = SENT; }
        if (isCons) { svU0 = hand_s[w - 1][jc]; miU0 = hand_m[w - 1][jc]; }
        const float dg0s = svD0;
        const int dg0m = miD0;
        svD0 = svU0;
        miD0 = miU0;

        const float4 cv = scol[jc];

        // row0 cell
        const PV n0 = cell(svU0, miU0, dg0s, dg0m, svC0, miC0,
                           xi0, dxa0, Ea0, Ea0K, cv);
        // row1 cell: up = n0 (same step), diag = old row0 (j-1), left = own
        const PV n1 = cell(n0.sv, n0.mi, svC0, miC0, svC1, miC1,
                           xi1, dxa1, Ea1, Ea1K, cv);
        if (active) {
            svC0 = n0.sv; miC0 = n0.mi;
            svC1 = n1.sv; miC1 = n1.mi;
        }

        if (isProd) { hand_s[w][jc] = svC1; hand_m[w][jc] = miC1; }
        if (isProd && active && ((j & (CHUNK - 1)) == CHUNK - 1)) {
            __threadfence_block();
            flags[w] = j + 1;
        }
    }

    if (t == 255) {  // row 511 final: C = -(mi + log2(sv)) * ln2
        g_costs[b] = -((float)miC1 + __log2f(svC1)) * LN2;
        __threadfence();
        const int old = atomicAdd(&g_done, 1);
        if (old == NBATCH - 1) {
            __threadfence();
            float v = 0.0f;
#pragma unroll
            for (int i = 0; i < NBATCH; ++i) v += g_costs[i];
            out[0] = v * (1.0f / (float)NBATCH);
            atomicExch(&g_done, 0);
        }
    }
}

extern "C" void kernel_launch(void* const* d_in, const int* in_sizes, int n_in,
                              void* d_out, int out_size) {
    const float* x = (const float*)d_in[0];
    const float* y = (const float*)d_in[1];
    float* out = (float*)d_out;
    soft_msm_kernel<<<NBATCH, 256>>>(x, y, out);
}